// round 1
// baseline (speedup 1.0000x reference)
#include <cuda_runtime.h>

#define NTOK 8192
#define DIM  1024
#define NE   8

#define BM 64
#define BN 64
#define BK 16

// ---------------- scratch (device globals: allocation-free rule) --------------
__device__ int   g_counts[NE];
__device__ int   g_list[NE][NTOK];     // entry = token*2 + slot
__device__ float g_listc[NE][NTOK];    // coefficient for that entry
__device__ int   g_tok_e[NTOK * 2];    // per-token expert ids (slot 0/1)
__device__ float g_tok_c[NTOK * 2];    // per-token coefficients
__device__ float g_scratch[(size_t)NTOK * 2 * DIM];   // 64 MB partial results

// ---------------- kernel 0: zero expert counters ------------------------------
__global__ void k_zero() {
    if (threadIdx.x < NE) g_counts[threadIdx.x] = 0;
}

// ---------------- kernel 1: gating (scores -> softmax -> top2 -> lists) -------
__global__ void k_gate(const float* __restrict__ x,
                       const float* __restrict__ gW,
                       const float* __restrict__ gb) {
    // gate_W transposed into smem: sWT[e][d] for conflict-free inner loads
    __shared__ float sWT[NE * DIM];
    for (int i = threadIdx.x; i < NE * DIM; i += blockDim.x) {
        int d = i >> 3, e = i & 7;           // gW is [D][E]
        sWT[e * DIM + d] = gW[i];
    }
    __syncthreads();

    int warp = threadIdx.x >> 5, lane = threadIdx.x & 31;
    int t = blockIdx.x * 8 + warp;           // grid = NTOK/8 blocks of 8 warps
    const float* xr = x + (size_t)t * DIM;

    float acc[NE];
#pragma unroll
    for (int e = 0; e < NE; e++) acc[e] = 0.f;

    for (int d = lane; d < DIM; d += 32) {
        float xv = xr[d];
#pragma unroll
        for (int e = 0; e < NE; e++) acc[e] = fmaf(xv, sWT[e * DIM + d], acc[e]);
    }
#pragma unroll
    for (int e = 0; e < NE; e++) {
#pragma unroll
        for (int o = 16; o; o >>= 1) acc[e] += __shfl_xor_sync(0xffffffffu, acc[e], o);
    }

    if (lane == 0) {
        // scores = max((x@W + b)/TEMP, EPS), TEMP=1, EPS=1e-4
        float s[NE], m = -1e30f;
#pragma unroll
        for (int e = 0; e < NE; e++) {
            s[e] = fmaxf(acc[e] + gb[e], 1e-4f);
            m = fmaxf(m, s[e]);
        }
        float p[NE], sum = 0.f;
#pragma unroll
        for (int e = 0; e < NE; e++) { p[e] = expf(s[e] - m); sum += p[e]; }
        float inv = 1.f / sum;
#pragma unroll
        for (int e = 0; e < NE; e++) p[e] *= inv;

        // top-2, earliest index wins ties (matches jax.lax.top_k)
        int i0 = 0;
#pragma unroll
        for (int e = 1; e < NE; e++) if (p[e] > p[i0]) i0 = e;
        int i1 = (i0 == 0) ? 1 : 0;
#pragma unroll
        for (int e = 0; e < NE; e++) if (e != i0 && p[e] > p[i1]) i1 = e;

        float w0 = fmaxf(p[i0], 0.1f);
        float w1 = fmaxf(p[i1], 0.1f);
        float inv2 = 1.f / (w0 + w1);
        float c0 = w0 * inv2 * 0.5f;   // comb/K, K=2
        float c1 = w1 * inv2 * 0.5f;

        int p0 = atomicAdd(&g_counts[i0], 1);
        g_list[i0][p0] = t * 2;     g_listc[i0][p0] = c0;
        int p1 = atomicAdd(&g_counts[i1], 1);
        g_list[i1][p1] = t * 2 + 1; g_listc[i1][p1] = c1;

        g_tok_e[t * 2]     = i0; g_tok_c[t * 2]     = c0;
        g_tok_e[t * 2 + 1] = i1; g_tok_c[t * 2 + 1] = c1;
    }
}

// ---------------- kernel 2: grouped expert GEMM (f32x2 packed FMA) ------------
// For expert e, rows = gathered tokens from g_list[e], B = expert_W[e] (d x f).
// Writes  coef * (x_row @ W_e)  into g_scratch[entry].
__global__ void __launch_bounds__(256) k_gemm(const float* __restrict__ x,
                                              const float* __restrict__ eW) {
    __shared__ float As[BK][BM + 4];   // [k][m], padded
    __shared__ float Bs[BK][BN];       // [k][f]
    __shared__ int   stok[BM];
    __shared__ float scoef[BM];

    int e   = blockIdx.z;
    int cnt = g_counts[e];
    int m0  = blockIdx.y * BM;
    if (m0 >= cnt) return;
    int n0  = blockIdx.x * BN;
    int tid = threadIdx.x;

    if (tid < BM) {
        int m = m0 + tid;
        if (m < cnt) { stok[tid] = g_list[e][m]; scoef[tid] = g_listc[e][m]; }
        else         { stok[tid] = -1;           scoef[tid] = 0.f; }
    }
    __syncthreads();

    // A-load mapping: 64 rows x 4 float4 chunks of k
    int lm  = tid >> 2;
    int lk4 = (tid & 3) * 4;
    // B-load mapping: 16 d-rows x 16 float4 chunks of f
    int brow = tid >> 4;
    int bcol = (tid & 15) * 4;
    // compute mapping: 16x16 threads, 4x4 outputs each
    int ty = tid >> 4;
    int tx = tid & 15;

    const float* wbase = eW + (size_t)e * DIM * DIM;
    int atok = stok[lm];
    const float* arow = x + (size_t)((atok >= 0 ? atok : 0) >> 1) * DIM;

    unsigned long long accp[4][2];     // 4 rows x 2 f32x2 col-pairs
#pragma unroll
    for (int i = 0; i < 4; i++) { accp[i][0] = 0ull; accp[i][1] = 0ull; }

    for (int k0 = 0; k0 < DIM; k0 += BK) {
        float4 av = *(const float4*)(arow + k0 + lk4);
        if (atok < 0) av = make_float4(0.f, 0.f, 0.f, 0.f);
        float4 bv = *(const float4*)(wbase + (size_t)(k0 + brow) * DIM + n0 + bcol);

        __syncthreads();   // previous tile's compute done
        As[lk4 + 0][lm] = av.x;
        As[lk4 + 1][lm] = av.y;
        As[lk4 + 2][lm] = av.z;
        As[lk4 + 3][lm] = av.w;
        *(float4*)&Bs[brow][bcol] = bv;
        __syncthreads();

#pragma unroll
        for (int k = 0; k < BK; k++) {
            float4 a4 = *(const float4*)&As[k][ty * 4];
            ulonglong2 b2 = *(const ulonglong2*)&Bs[k][tx * 4];
#define FF(i, aval)                                                              \
            {                                                                    \
                unsigned long long ad;                                           \
                asm("mov.b64 %0, {%1, %1};" : "=l"(ad)                           \
                    : "r"(__float_as_uint(aval)));                               \
                asm("fma.rn.f32x2 %0, %1, %2, %0;" : "+l"(accp[i][0])            \
                    : "l"(ad), "l"(b2.x));                                       \
                asm("fma.rn.f32x2 %0, %1, %2, %0;" : "+l"(accp[i][1])            \
                    : "l"(ad), "l"(b2.y));                                       \
            }
            FF(0, a4.x) FF(1, a4.y) FF(2, a4.z) FF(3, a4.w)
#undef FF
        }
    }

    // epilogue: scale by coefficient, store to scratch row for (token,slot)
#pragma unroll
    for (int i = 0; i < 4; i++) {
        int mm = ty * 4 + i;
        if (m0 + mm < cnt) {
            int entry = stok[mm];
            float c = scoef[mm];
            unsigned int l0, h0, l1, h1;
            asm("mov.b64 {%0, %1}, %2;" : "=r"(l0), "=r"(h0) : "l"(accp[i][0]));
            asm("mov.b64 {%0, %1}, %2;" : "=r"(l1), "=r"(h1) : "l"(accp[i][1]));
            float4 r;
            r.x = __uint_as_float(l0) * c;
            r.y = __uint_as_float(h0) * c;
            r.z = __uint_as_float(l1) * c;
            r.w = __uint_as_float(h1) * c;
            *(float4*)(g_scratch + (size_t)entry * DIM + n0 + tx * 4) = r;
        }
    }
}

// ---------------- kernel 3: combine two slots + bias --------------------------
__global__ void k_combine(const float* __restrict__ eb, float* __restrict__ out) {
    int t = blockIdx.x;
    int e0 = g_tok_e[2 * t], e1 = g_tok_e[2 * t + 1];
    float c0 = g_tok_c[2 * t], c1 = g_tok_c[2 * t + 1];
    const float* s0 = g_scratch + (size_t)(2 * t) * DIM;
    const float* s1 = g_scratch + (size_t)(2 * t + 1) * DIM;
    const float* b0 = eb + (size_t)e0 * DIM;
    const float* b1 = eb + (size_t)e1 * DIM;
    float* o = out + (size_t)t * DIM;
    for (int f = threadIdx.x * 4; f < DIM; f += blockDim.x * 4) {
        float4 v0 = *(const float4*)(s0 + f);
        float4 v1 = *(const float4*)(s1 + f);
        float4 bb0 = *(const float4*)(b0 + f);
        float4 bb1 = *(const float4*)(b1 + f);
        float4 r;
        r.x = v0.x + v1.x + c0 * bb0.x + c1 * bb1.x;
        r.y = v0.y + v1.y + c0 * bb0.y + c1 * bb1.y;
        r.z = v0.z + v1.z + c0 * bb0.z + c1 * bb1.z;
        r.w = v0.w + v1.w + c0 * bb0.w + c1 * bb1.w;
        *(float4*)(o + f) = r;
    }
}

// ---------------- launch ------------------------------------------------------
extern "C" void kernel_launch(void* const* d_in, const int* in_sizes, int n_in,
                              void* d_out, int out_size) {
    const float* x  = (const float*)d_in[0];
    const float* gW = (const float*)d_in[1];
    const float* gb = (const float*)d_in[2];
    const float* eW = (const float*)d_in[3];
    const float* eb = (const float*)d_in[4];
    float* out = (float*)d_out;

    k_zero<<<1, 32>>>();
    k_gate<<<NTOK / 8, 256>>>(x, gW, gb);
    dim3 grid(DIM / BN, NTOK / BM, NE);   // (16, 128, 8); empty tiles exit early
    k_gemm<<<grid, 256>>>(x, eW);
    k_combine<<<NTOK, 256>>>(eb, out);
}

// round 6
// speedup vs baseline: 2.2278x; 2.2278x over previous
#include <cuda_runtime.h>
#include <cstdint>

#define NTOK 8192
#define DIM  1024
#define NE   8

// GEMM tiling
#define BM 128
#define BN 128
#define BK 32
#define NK (DIM / BK)          // 32
#define NST 4                  // cp.async stages

#define ASTRIDE 36             // floats per padded smem row (144B)
#define A_F (BM * ASTRIDE)     // 4608 floats
#define STAGE_F (2 * A_F)      // A + B per stage = 9216 floats
#define STAGE_B (STAGE_F * 4)  // 36864 bytes
#define SMEM_TOK_OFF (NST * STAGE_B)           // 147456
#define SMEM_COEF_OFF (SMEM_TOK_OFF + BM * 4)  // 147968
#define SMEM_TOTAL (SMEM_COEF_OFF + BM * 4)    // 148480

// ---------------- device scratch (allocation-free rule) -----------------------
__device__ int   g_counts[NE];
__device__ int   g_list[NE][NTOK];     // entry = token*2 + slot
__device__ float g_listc[NE][NTOK];
__device__ int   g_tok_e[NTOK * 2];
__device__ float g_tok_c[NTOK * 2];
__device__ float g_xr[(size_t)NTOK * DIM];            // x rounded to tf32
__device__ float g_wt[(size_t)NE * DIM * DIM];        // W^T tf32-rounded: [e][f][d]
__device__ float g_scratch[(size_t)NTOK * 2 * DIM];   // per-(token,slot) partials

// ---------------- helpers -----------------------------------------------------
__device__ __forceinline__ uint32_t smem_u32(const void* p) {
    uint32_t a;
    asm("{ .reg .u64 t; cvta.to.shared.u64 t, %1; cvt.u32.u64 %0, t; }" : "=r"(a) : "l"(p));
    return a;
}
__device__ __forceinline__ float round_tf32(float v) {
    uint32_t r;
    asm("cvt.rna.tf32.f32 %0, %1;" : "=r"(r) : "f"(v));
    return __uint_as_float(r);
}
__device__ __forceinline__ void cpa16(uint32_t dst, const void* src) {
    asm volatile("cp.async.cg.shared.global [%0], [%1], 16;" :: "r"(dst), "l"(src) : "memory");
}
__device__ __forceinline__ void mma8(float* c, uint32_t a0, uint32_t a1, uint32_t a2,
                                     uint32_t a3, uint32_t b0, uint32_t b1) {
    asm volatile(
        "mma.sync.aligned.m16n8k8.row.col.f32.tf32.tf32.f32 "
        "{%0,%1,%2,%3}, {%4,%5,%6,%7}, {%8,%9}, {%0,%1,%2,%3};"
        : "+f"(c[0]), "+f"(c[1]), "+f"(c[2]), "+f"(c[3])
        : "r"(a0), "r"(a1), "r"(a2), "r"(a3), "r"(b0), "r"(b1));
}

// ---------------- kernel 0: zero counters -------------------------------------
__global__ void k_zero() {
    if (threadIdx.x < NE) g_counts[threadIdx.x] = 0;
}

// ---------------- kernel 1: round x to tf32 -----------------------------------
__global__ void k_round(const float* __restrict__ x) {
    size_t i = ((size_t)blockIdx.x * blockDim.x + threadIdx.x) * 4;
    float4 v = *(const float4*)(x + i);
    v.x = round_tf32(v.x); v.y = round_tf32(v.y);
    v.z = round_tf32(v.z); v.w = round_tf32(v.w);
    *(float4*)(g_xr + i) = v;
}

// ---------------- kernel 2: transpose W -> [e][f][d], tf32-rounded -------------
__global__ void k_transpose(const float* __restrict__ eW) {
    __shared__ float tile[32][33];
    int e = blockIdx.z;
    int d0 = blockIdx.y * 32, f0 = blockIdx.x * 32;
    const float* src = eW + (size_t)e * DIM * DIM;
    float* dst = g_wt + (size_t)e * DIM * DIM;
    int tx = threadIdx.x, ty = threadIdx.y;   // 32 x 8
#pragma unroll
    for (int i = 0; i < 32; i += 8)
        tile[ty + i][tx] = round_tf32(src[(size_t)(d0 + ty + i) * DIM + f0 + tx]);
    __syncthreads();
#pragma unroll
    for (int i = 0; i < 32; i += 8)
        dst[(size_t)(f0 + ty + i) * DIM + d0 + tx] = tile[tx][ty + i];
}

// ---------------- kernel 3: gating --------------------------------------------
__global__ void k_gate(const float* __restrict__ x,
                       const float* __restrict__ gW,
                       const float* __restrict__ gb) {
    __shared__ float sWT[NE * DIM];
    for (int i = threadIdx.x; i < NE * DIM; i += blockDim.x) {
        int d = i >> 3, e = i & 7;
        sWT[e * DIM + d] = gW[i];
    }
    __syncthreads();

    int warp = threadIdx.x >> 5, lane = threadIdx.x & 31;
    int t = blockIdx.x * 8 + warp;
    const float* xr = x + (size_t)t * DIM;

    float acc[NE];
#pragma unroll
    for (int e = 0; e < NE; e++) acc[e] = 0.f;
    for (int d = lane; d < DIM; d += 32) {
        float xv = xr[d];
#pragma unroll
        for (int e = 0; e < NE; e++) acc[e] = fmaf(xv, sWT[e * DIM + d], acc[e]);
    }
#pragma unroll
    for (int e = 0; e < NE; e++) {
#pragma unroll
        for (int o = 16; o; o >>= 1) acc[e] += __shfl_xor_sync(0xffffffffu, acc[e], o);
    }

    if (lane == 0) {
        float s[NE], m = -1e30f;
#pragma unroll
        for (int e = 0; e < NE; e++) { s[e] = fmaxf(acc[e] + gb[e], 1e-4f); m = fmaxf(m, s[e]); }
        float p[NE], sum = 0.f;
#pragma unroll
        for (int e = 0; e < NE; e++) { p[e] = expf(s[e] - m); sum += p[e]; }
        float inv = 1.f / sum;
#pragma unroll
        for (int e = 0; e < NE; e++) p[e] *= inv;

        int i0 = 0;
#pragma unroll
        for (int e = 1; e < NE; e++) if (p[e] > p[i0]) i0 = e;
        int i1 = (i0 == 0) ? 1 : 0;
#pragma unroll
        for (int e = 0; e < NE; e++) if (e != i0 && p[e] > p[i1]) i1 = e;

        float w0 = fmaxf(p[i0], 0.1f);
        float w1 = fmaxf(p[i1], 0.1f);
        float inv2 = 1.f / (w0 + w1);
        float c0 = w0 * inv2 * 0.5f;
        float c1 = w1 * inv2 * 0.5f;

        int p0 = atomicAdd(&g_counts[i0], 1);
        g_list[i0][p0] = t * 2;     g_listc[i0][p0] = c0;
        int p1 = atomicAdd(&g_counts[i1], 1);
        g_list[i1][p1] = t * 2 + 1; g_listc[i1][p1] = c1;

        g_tok_e[t * 2] = i0;     g_tok_c[t * 2] = c0;
        g_tok_e[t * 2 + 1] = i1; g_tok_c[t * 2 + 1] = c1;
    }
}

// ---------------- kernel 4: grouped GEMM, mma.sync tf32 ------------------------
__global__ void __launch_bounds__(256, 1) k_gemm() {
    extern __shared__ float smf[];
    int e   = blockIdx.z;
    int cnt = g_counts[e];
    int m0  = blockIdx.y * BM;
    if (m0 >= cnt) return;
    int n0  = blockIdx.x * BN;

    char* smc = (char*)smf;
    int*   stok  = (int*)(smc + SMEM_TOK_OFF);
    float* scoef = (float*)(smc + SMEM_COEF_OFF);
    uint32_t sbase = smem_u32(smf);

    int tid  = threadIdx.x;
    int warp = tid >> 5;
    int lane = tid & 31;
    int g    = lane >> 2;     // fragment group row / n
    int t4   = lane & 3;      // fragment k index

    if (tid < BM) {
        int m = m0 + tid;
        if (m < cnt) { stok[tid] = g_list[e][m]; scoef[tid] = g_listc[e][m]; }
        else         { stok[tid] = -1;           scoef[tid] = 0.f; }
    }
    __syncthreads();

    // warp tile: 2 (m) x 4 (n), WM=64, WN=32
    int wm = (warp >> 2) * 64;
    int wn = (warp & 3) * 32;

    // global load mapping: 2 threads per row, 4x 16B chunks each (128B row)
    int lrow = tid >> 1, lh = tid & 1;
    int atok = stok[lrow];
    const float* asrc = g_xr + (size_t)((atok >= 0 ? atok : 0) >> 1) * DIM + lh * 16;
    const float* bsrc = g_wt + (size_t)e * DIM * DIM + (size_t)(n0 + lrow) * DIM + lh * 16;
    uint32_t adst = sbase + lrow * 144 + lh * 64;
    uint32_t bdst = adst + A_F * 4;

#define LOAD_STAGE(kc_, st_)                                                   \
    {                                                                          \
        uint32_t so_ = (st_) * STAGE_B;                                        \
        const float* as_ = asrc + (kc_) * BK;                                  \
        const float* bs_ = bsrc + (kc_) * BK;                                  \
        _Pragma("unroll")                                                      \
        for (int j = 0; j < 4; j++) {                                          \
            cpa16(adst + so_ + j * 16, as_ + j * 4);                           \
            cpa16(bdst + so_ + j * 16, bs_ + j * 4);                           \
        }                                                                      \
        asm volatile("cp.async.commit_group;" ::: "memory");                   \
    }

#pragma unroll
    for (int s = 0; s < NST - 1; s++) LOAD_STAGE(s, s);

    float acc[2][4][4];
#pragma unroll
    for (int mt = 0; mt < 2; mt++)
#pragma unroll
        for (int nt = 0; nt < 4; nt++)
#pragma unroll
            for (int i = 0; i < 4; i++) acc[mt][nt][i] = 0.f;

    for (int kc = 0; kc < NK; kc++) {
        asm volatile("cp.async.wait_group %0;" :: "n"(NST - 2) : "memory");
        __syncthreads();

        const float* As = smf + (kc & (NST - 1)) * STAGE_F;
        const float* Bs = As + A_F;
        const float* ar = As + (wm + g) * ASTRIDE + t4;
        const float* br = Bs + (wn + g) * ASTRIDE + t4;

#pragma unroll
        for (int ks = 0; ks < BK / 8; ks++) {
            int kl = ks * 8;
            uint32_t a[2][2][4];   // mt(2x32rows? no: mt covers 64 rows via 16-step)
            // 4 m-tiles of 16 rows each within WM=64 -> pack as [4]
            uint32_t af[4][4], bf[4][2];
#pragma unroll
            for (int mt = 0; mt < 4; mt++) {
                const float* p = ar + mt * (16 * ASTRIDE) + kl;
                af[mt][0] = __float_as_uint(p[0]);
                af[mt][1] = __float_as_uint(p[8 * ASTRIDE]);
                af[mt][2] = __float_as_uint(p[4]);
                af[mt][3] = __float_as_uint(p[8 * ASTRIDE + 4]);
            }
#pragma unroll
            for (int nt = 0; nt < 4; nt++) {
                const float* p = br + nt * (8 * ASTRIDE) + kl;
                bf[nt][0] = __float_as_uint(p[0]);
                bf[nt][1] = __float_as_uint(p[4]);
            }
#pragma unroll
            for (int mt = 0; mt < 4; mt++)
#pragma unroll
                for (int nt = 0; nt < 4; nt++)
                    mma8(acc[mt >> 1][nt] + ((mt & 1) ? 0 : 0),   // placeholder, fixed below
                         af[mt][0], af[mt][1], af[mt][2], af[mt][3],
                         bf[nt][0], bf[nt][1]);
            (void)a;
        }

        int kn = kc + NST - 1;
        if (kn < NK) {
            LOAD_STAGE(kn, kn & (NST - 1));
        } else {
            asm volatile("cp.async.commit_group;" ::: "memory");
        }
    }

    // NOTE on acc indexing: the mma loop above must accumulate into a distinct
    // accumulator per (mt, nt).  acc is [2][4][4] but we have 4 m-tiles; this
    // placeholder collapses pairs.  Replaced by correct 4-tile version:
    // (see acc4 below -- the code above is structured so the compiler never
    //  emits it; real implementation follows)
    ;
    // ---- epilogue ----
#pragma unroll
    for (int mt = 0; mt < 2; mt++) {
#pragma unroll
        for (int half = 0; half < 2; half++) {
            int m = wm + (mt * 2 + half) * 16 + g;   // placeholder
            (void)m;
        }
    }
    // real epilogue in k_gemm2
}

// ---------------- kernel 4 (real): grouped GEMM, mma.sync tf32 -----------------
__global__ void __launch_bounds__(256, 1) k_gemm2() {
    extern __shared__ float smf[];
    int e   = blockIdx.z;
    int cnt = g_counts[e];
    int m0  = blockIdx.y * BM;
    if (m0 >= cnt) return;
    int n0  = blockIdx.x * BN;

    char* smc = (char*)smf;
    int*   stok  = (int*)(smc + SMEM_TOK_OFF);
    float* scoef = (float*)(smc + SMEM_COEF_OFF);
    uint32_t sbase = smem_u32(smf);

    int tid  = threadIdx.x;
    int warp = tid >> 5;
    int lane = tid & 31;
    int g    = lane >> 2;
    int t4   = lane & 3;

    if (tid < BM) {
        int m = m0 + tid;
        if (m < cnt) { stok[tid] = g_list[e][m]; scoef[tid] = g_listc[e][m]; }
        else         { stok[tid] = -1;           scoef[tid] = 0.f; }
    }
    __syncthreads();

    int wm = (warp >> 2) * 64;
    int wn = (warp & 3) * 32;

    int lrow = tid >> 1, lh = tid & 1;
    int atok = stok[lrow];
    const float* asrc = g_xr + (size_t)((atok >= 0 ? atok : 0) >> 1) * DIM + lh * 16;
    const float* bsrc = g_wt + (size_t)e * DIM * DIM + (size_t)(n0 + lrow) * DIM + lh * 16;
    uint32_t adst = sbase + lrow * 144 + lh * 64;
    uint32_t bdst = adst + A_F * 4;

#pragma unroll
    for (int s = 0; s < NST - 1; s++) LOAD_STAGE(s, s);

    float acc[4][4][4];
#pragma unroll
    for (int mt = 0; mt < 4; mt++)
#pragma unroll
        for (int nt = 0; nt < 4; nt++)
#pragma unroll
            for (int i = 0; i < 4; i++) acc[mt][nt][i] = 0.f;

    for (int kc = 0; kc < NK; kc++) {
        asm volatile("cp.async.wait_group %0;" :: "n"(NST - 2) : "memory");
        __syncthreads();

        const float* As = smf + (kc & (NST - 1)) * STAGE_F;
        const float* Bs = As + A_F;
        const float* ar = As + (wm + g) * ASTRIDE + t4;
        const float* br = Bs + (wn + g) * ASTRIDE + t4;

#pragma unroll
        for (int ks = 0; ks < BK / 8; ks++) {
            int kl = ks * 8;
            uint32_t af[4][4], bf[4][2];
#pragma unroll
            for (int mt = 0; mt < 4; mt++) {
                const float* p = ar + mt * (16 * ASTRIDE) + kl;
                af[mt][0] = __float_as_uint(p[0]);
                af[mt][1] = __float_as_uint(p[8 * ASTRIDE]);
                af[mt][2] = __float_as_uint(p[4]);
                af[mt][3] = __float_as_uint(p[8 * ASTRIDE + 4]);
            }
#pragma unroll
            for (int nt = 0; nt < 4; nt++) {
                const float* p = br + nt * (8 * ASTRIDE) + kl;
                bf[nt][0] = __float_as_uint(p[0]);
                bf[nt][1] = __float_as_uint(p[4]);
            }
#pragma unroll
            for (int mt = 0; mt < 4; mt++)
#pragma unroll
                for (int nt = 0; nt < 4; nt++)
                    mma8(acc[mt][nt], af[mt][0], af[mt][1], af[mt][2], af[mt][3],
                         bf[nt][0], bf[nt][1]);
        }

        int kn = kc + NST - 1;
        if (kn < NK) {
            LOAD_STAGE(kn, kn & (NST - 1));
        } else {
            asm volatile("cp.async.commit_group;" ::: "memory");
        }
    }

    // epilogue: scale rows by coef, scatter to g_scratch
#pragma unroll
    for (int mt = 0; mt < 4; mt++) {
#pragma unroll
        for (int half = 0; half < 2; half++) {
            int m = wm + mt * 16 + half * 8 + g;
            if (m0 + m < cnt) {
                int entry = stok[m];
                float cf  = scoef[m];
                float* orow = g_scratch + (size_t)entry * DIM + n0 + wn;
#pragma unroll
                for (int nt = 0; nt < 4; nt++) {
                    float2 v;
                    v.x = acc[mt][nt][half * 2 + 0] * cf;
                    v.y = acc[mt][nt][half * 2 + 1] * cf;
                    *(float2*)(orow + nt * 8 + t4 * 2) = v;
                }
            }
        }
    }
}

// ---------------- kernel 5: combine two slots + bias ---------------------------
__global__ void k_combine(const float* __restrict__ eb, float* __restrict__ out) {
    int t = blockIdx.x;
    int e0 = g_tok_e[2 * t], e1 = g_tok_e[2 * t + 1];
    float c0 = g_tok_c[2 * t], c1 = g_tok_c[2 * t + 1];
    const float* s0 = g_scratch + (size_t)(2 * t) * DIM;
    const float* s1 = g_scratch + (size_t)(2 * t + 1) * DIM;
    const float* b0 = eb + (size_t)e0 * DIM;
    const float* b1 = eb + (size_t)e1 * DIM;
    float* o = out + (size_t)t * DIM;
    for (int f = threadIdx.x * 4; f < DIM; f += blockDim.x * 4) {
        float4 v0 = *(const float4*)(s0 + f);
        float4 v1 = *(const float4*)(s1 + f);
        float4 bb0 = *(const float4*)(b0 + f);
        float4 bb1 = *(const float4*)(b1 + f);
        float4 r;
        r.x = v0.x + v1.x + c0 * bb0.x + c1 * bb1.x;
        r.y = v0.y + v1.y + c0 * bb0.y + c1 * bb1.y;
        r.z = v0.z + v1.z + c0 * bb0.z + c1 * bb1.z;
        r.w = v0.w + v1.w + c0 * bb0.w + c1 * bb1.w;
        *(float4*)(o + f) = r;
    }
}

// ---------------- launch -------------------------------------------------------
extern "C" void kernel_launch(void* const* d_in, const int* in_sizes, int n_in,
                              void* d_out, int out_size) {
    const float* x  = (const float*)d_in[0];
    const float* gW = (const float*)d_in[1];
    const float* gb = (const float*)d_in[2];
    const float* eW = (const float*)d_in[3];
    const float* eb = (const float*)d_in[4];
    float* out = (float*)d_out;

    cudaFuncSetAttribute(k_gemm2, cudaFuncAttributeMaxDynamicSharedMemorySize, SMEM_TOTAL);

    k_zero<<<1, 32>>>();
    k_round<<<(NTOK * DIM) / (512 * 4), 512>>>(x);
    dim3 tgrid(DIM / 32, DIM / 32, NE);
    k_transpose<<<tgrid, dim3(32, 8)>>>(eW);
    k_gate<<<NTOK / 8, 256>>>(x, gW, gb);
    dim3 grid(DIM / BN, NTOK / BM, NE);      // (8, 64, 8); empty tiles exit early
    k_gemm2<<<grid, 256, SMEM_TOTAL>>>();
    k_combine<<<NTOK, 256>>>(eb, out);
}

// round 9
// speedup vs baseline: 3.2713x; 1.4684x over previous
#include <cuda_runtime.h>
#include <cuda_fp16.h>
#include <cstdint>

#define NTOK 8192
#define DIM  1024
#define NE   8

// GEMM tiling (fp16 operands, fp32 accum)
#define BM 128
#define BN 128
#define BK 64                  // halves per k-chunk
#define NK (DIM / BK)          // 16
#define NST 4                  // cp.async stages

#define RSTRIDE_H 72           // halves per padded smem row (144B)
#define ROW_B 144
#define STAGE_B (256 * ROW_B)  // A(128 rows) + B(128 rows) = 36864 B
#define SMEM_TOK_OFF (NST * STAGE_B)            // 147456
#define SMEM_COEF_OFF (SMEM_TOK_OFF + BM * 4)   // 147968
#define SMEM_TOTAL (SMEM_COEF_OFF + BM * 4)     // 148480

// ---------------- device scratch (allocation-free rule) -----------------------
__device__ int    g_counts[NE];
__device__ int    g_list[NE][NTOK];     // entry = token*2 + slot
__device__ float  g_listc[NE][NTOK];
__device__ int    g_tok_e[NTOK * 2];
__device__ float  g_tok_c[NTOK * 2];
__device__ __half g_xh[(size_t)NTOK * DIM];           // x in fp16
__device__ __half g_wh[(size_t)NE * DIM * DIM];       // W^T in fp16: [e][f][d]
__device__ float  g_scratch[(size_t)NTOK * 2 * DIM];  // per-(token,slot) partials

// ---------------- helpers -----------------------------------------------------
__device__ __forceinline__ uint32_t smem_u32(const void* p) {
    uint32_t a;
    asm("{ .reg .u64 t; cvta.to.shared.u64 t, %1; cvt.u32.u64 %0, t; }" : "=r"(a) : "l"(p));
    return a;
}
__device__ __forceinline__ void cpa16(uint32_t dst, const void* src) {
    asm volatile("cp.async.cg.shared.global [%0], [%1], 16;" :: "r"(dst), "l"(src) : "memory");
}
__device__ __forceinline__ void mma16(float* c, uint32_t a0, uint32_t a1, uint32_t a2,
                                      uint32_t a3, uint32_t b0, uint32_t b1) {
    asm volatile(
        "mma.sync.aligned.m16n8k16.row.col.f32.f16.f16.f32 "
        "{%0,%1,%2,%3}, {%4,%5,%6,%7}, {%8,%9}, {%0,%1,%2,%3};"
        : "+f"(c[0]), "+f"(c[1]), "+f"(c[2]), "+f"(c[3])
        : "r"(a0), "r"(a1), "r"(a2), "r"(a3), "r"(b0), "r"(b1));
}

// ---------------- kernel 1: x -> fp16 (+ zero counters) ------------------------
__global__ void k_round(const float* __restrict__ x) {
    if (blockIdx.x == 0 && threadIdx.x < NE) g_counts[threadIdx.x] = 0;
    size_t i = ((size_t)blockIdx.x * blockDim.x + threadIdx.x) * 8;
    float4 v0 = *(const float4*)(x + i);
    float4 v1 = *(const float4*)(x + i + 4);
    __half2 h[4];
    h[0] = __floats2half2_rn(v0.x, v0.y);
    h[1] = __floats2half2_rn(v0.z, v0.w);
    h[2] = __floats2half2_rn(v1.x, v1.y);
    h[3] = __floats2half2_rn(v1.z, v1.w);
    *(uint4*)(g_xh + i) = *(uint4*)h;
}

// ---------------- kernel 2: transpose W -> [e][f][d] fp16 ----------------------
__global__ void k_transpose(const float* __restrict__ eW) {
    __shared__ float tile[32][33];
    int e = blockIdx.z;
    int d0 = blockIdx.y * 32, f0 = blockIdx.x * 32;
    const float* src = eW + (size_t)e * DIM * DIM;
    __half* dst = g_wh + (size_t)e * DIM * DIM;
    int tx = threadIdx.x, ty = threadIdx.y;   // 32 x 8
#pragma unroll
    for (int i = 0; i < 32; i += 8)
        tile[ty + i][tx] = src[(size_t)(d0 + ty + i) * DIM + f0 + tx];
    __syncthreads();
#pragma unroll
    for (int i = 0; i < 32; i += 8)
        dst[(size_t)(f0 + ty + i) * DIM + d0 + tx] = __float2half_rn(tile[tx][ty + i]);
}

// ---------------- kernel 3: gating (4 tokens per warp) --------------------------
__global__ void k_gate(const float* __restrict__ x,
                       const float* __restrict__ gW,
                       const float* __restrict__ gb) {
    __shared__ float sWT[NE * DIM];
    for (int i = threadIdx.x; i < NE * DIM; i += blockDim.x) {
        int d = i >> 3, e = i & 7;          // gW is [D][E]
        sWT[e * DIM + d] = gW[i];
    }
    __syncthreads();

    int warp = threadIdx.x >> 5, lane = threadIdx.x & 31;
    int t0 = blockIdx.x * 32 + warp * 4;    // 4 tokens per warp

    float acc[4][NE];
#pragma unroll
    for (int tt = 0; tt < 4; tt++)
#pragma unroll
        for (int e = 0; e < NE; e++) acc[tt][e] = 0.f;

    for (int d = lane; d < DIM; d += 32) {
        float wv[NE];
#pragma unroll
        for (int e = 0; e < NE; e++) wv[e] = sWT[e * DIM + d];
#pragma unroll
        for (int tt = 0; tt < 4; tt++) {
            float xv = x[(size_t)(t0 + tt) * DIM + d];
#pragma unroll
            for (int e = 0; e < NE; e++) acc[tt][e] = fmaf(xv, wv[e], acc[tt][e]);
        }
    }
#pragma unroll
    for (int tt = 0; tt < 4; tt++)
#pragma unroll
        for (int e = 0; e < NE; e++)
#pragma unroll
            for (int o = 16; o; o >>= 1)
                acc[tt][e] += __shfl_xor_sync(0xffffffffu, acc[tt][e], o);

    if (lane == 0) {
#pragma unroll
        for (int tt = 0; tt < 4; tt++) {
            int t = t0 + tt;
            float s[NE], m = -1e30f;
#pragma unroll
            for (int e = 0; e < NE; e++) {
                s[e] = fmaxf(acc[tt][e] + gb[e], 1e-4f);
                m = fmaxf(m, s[e]);
            }
            float p[NE], sum = 0.f;
#pragma unroll
            for (int e = 0; e < NE; e++) { p[e] = expf(s[e] - m); sum += p[e]; }
            float inv = 1.f / sum;
#pragma unroll
            for (int e = 0; e < NE; e++) p[e] *= inv;

            int i0 = 0;
#pragma unroll
            for (int e = 1; e < NE; e++) if (p[e] > p[i0]) i0 = e;
            int i1 = (i0 == 0) ? 1 : 0;
#pragma unroll
            for (int e = 0; e < NE; e++) if (e != i0 && p[e] > p[i1]) i1 = e;

            float w0 = fmaxf(p[i0], 0.1f);
            float w1 = fmaxf(p[i1], 0.1f);
            float inv2 = 1.f / (w0 + w1);
            float c0 = w0 * inv2 * 0.5f;
            float c1 = w1 * inv2 * 0.5f;

            int p0 = atomicAdd(&g_counts[i0], 1);
            g_list[i0][p0] = t * 2;     g_listc[i0][p0] = c0;
            int p1 = atomicAdd(&g_counts[i1], 1);
            g_list[i1][p1] = t * 2 + 1; g_listc[i1][p1] = c1;

            g_tok_e[t * 2] = i0;     g_tok_c[t * 2] = c0;
            g_tok_e[t * 2 + 1] = i1; g_tok_c[t * 2 + 1] = c1;
        }
    }
}

// ---------------- kernel 4: grouped GEMM, mma.sync fp16 k16 --------------------
__global__ void __launch_bounds__(256, 1) k_gemm() {
    extern __shared__ char smc[];
    int e   = blockIdx.z;
    int cnt = g_counts[e];
    int m0  = blockIdx.y * BM;
    if (m0 >= cnt) return;
    int n0  = blockIdx.x * BN;

    int*   stok  = (int*)(smc + SMEM_TOK_OFF);
    float* scoef = (float*)(smc + SMEM_COEF_OFF);
    uint32_t sbase = smem_u32(smc);

    int tid  = threadIdx.x;
    int warp = tid >> 5;
    int lane = tid & 31;
    int g    = lane >> 2;
    int t4   = lane & 3;

    if (tid < BM) {
        int m = m0 + tid;
        if (m < cnt) { stok[tid] = g_list[e][m]; scoef[tid] = g_listc[e][m]; }
        else         { stok[tid] = -1;           scoef[tid] = 0.f; }
    }
    __syncthreads();

    int wm = (warp >> 2) * 64;   // warp tile 64 x 32
    int wn = (warp & 3) * 32;

    // global->smem mapping: thread tid owns smem row tid (A rows 0-127, B rows 128-255)
    const __half* gsrc;
    if (tid < BM) {
        int atok = stok[tid];
        gsrc = g_xh + (size_t)((atok >= 0 ? atok : 0) >> 1) * DIM;
    } else {
        gsrc = g_wh + (size_t)e * DIM * DIM + (size_t)(n0 + tid - BM) * DIM;
    }
    uint32_t rowdst = sbase + tid * ROW_B;

#define LOAD_STAGE(kc_, st_)                                                   \
    {                                                                          \
        uint32_t d_ = rowdst + (st_) * STAGE_B;                                \
        const __half* s_ = gsrc + (kc_) * BK;                                  \
        _Pragma("unroll")                                                      \
        for (int j = 0; j < 8; j++) cpa16(d_ + j * 16, s_ + j * 8);            \
        asm volatile("cp.async.commit_group;" ::: "memory");                   \
    }

#pragma unroll
    for (int s = 0; s < NST - 1; s++) LOAD_STAGE(s, s);

    float acc[4][4][4];
#pragma unroll
    for (int mt = 0; mt < 4; mt++)
#pragma unroll
        for (int nt = 0; nt < 4; nt++)
#pragma unroll
            for (int i = 0; i < 4; i++) acc[mt][nt][i] = 0.f;

    for (int kc = 0; kc < NK; kc++) {
        asm volatile("cp.async.wait_group %0;" :: "n"(NST - 2) : "memory");
        __syncthreads();

        const __half* stage = (const __half*)(smc + (kc & (NST - 1)) * STAGE_B);
        const __half* ar = stage + (size_t)(wm + g) * RSTRIDE_H + 2 * t4;
        const __half* br = stage + (size_t)(BM + wn + g) * RSTRIDE_H + 2 * t4;

#pragma unroll
        for (int ks = 0; ks < BK / 16; ks++) {
            int kl = ks * 16;
            uint32_t af[4][4], bf[4][2];
#pragma unroll
            for (int mt = 0; mt < 4; mt++) {
                const __half* p = ar + mt * (16 * RSTRIDE_H) + kl;
                af[mt][0] = *(const uint32_t*)(p);
                af[mt][1] = *(const uint32_t*)(p + 8 * RSTRIDE_H);
                af[mt][2] = *(const uint32_t*)(p + 8);
                af[mt][3] = *(const uint32_t*)(p + 8 * RSTRIDE_H + 8);
            }
#pragma unroll
            for (int nt = 0; nt < 4; nt++) {
                const __half* q = br + nt * (8 * RSTRIDE_H) + kl;
                bf[nt][0] = *(const uint32_t*)(q);
                bf[nt][1] = *(const uint32_t*)(q + 8);
            }
#pragma unroll
            for (int mt = 0; mt < 4; mt++)
#pragma unroll
                for (int nt = 0; nt < 4; nt++)
                    mma16(acc[mt][nt], af[mt][0], af[mt][1], af[mt][2], af[mt][3],
                          bf[nt][0], bf[nt][1]);
        }

        int kn = kc + NST - 1;
        if (kn < NK) {
            LOAD_STAGE(kn, kn & (NST - 1));
        } else {
            asm volatile("cp.async.commit_group;" ::: "memory");
        }
    }

    // epilogue: scale rows by coef, scatter to g_scratch
#pragma unroll
    for (int mt = 0; mt < 4; mt++) {
#pragma unroll
        for (int half = 0; half < 2; half++) {
            int m = wm + mt * 16 + half * 8 + g;
            if (m0 + m < cnt) {
                int entry = stok[m];
                float cf  = scoef[m];
                float* orow = g_scratch + (size_t)entry * DIM + n0 + wn;
#pragma unroll
                for (int nt = 0; nt < 4; nt++) {
                    float2 v;
                    v.x = acc[mt][nt][half * 2 + 0] * cf;
                    v.y = acc[mt][nt][half * 2 + 1] * cf;
                    *(float2*)(orow + nt * 8 + t4 * 2) = v;
                }
            }
        }
    }
}

// ---------------- kernel 5: combine two slots + bias ---------------------------
__global__ void k_combine(const float* __restrict__ eb, float* __restrict__ out) {
    int t = blockIdx.x;
    int e0 = g_tok_e[2 * t], e1 = g_tok_e[2 * t + 1];
    float c0 = g_tok_c[2 * t], c1 = g_tok_c[2 * t + 1];
    const float* s0 = g_scratch + (size_t)(2 * t) * DIM;
    const float* s1 = g_scratch + (size_t)(2 * t + 1) * DIM;
    const float* b0 = eb + (size_t)e0 * DIM;
    const float* b1 = eb + (size_t)e1 * DIM;
    float* o = out + (size_t)t * DIM;
    for (int f = threadIdx.x * 4; f < DIM; f += blockDim.x * 4) {
        float4 v0 = *(const float4*)(s0 + f);
        float4 v1 = *(const float4*)(s1 + f);
        float4 bb0 = *(const float4*)(b0 + f);
        float4 bb1 = *(const float4*)(b1 + f);
        float4 r;
        r.x = v0.x + v1.x + c0 * bb0.x + c1 * bb1.x;
        r.y = v0.y + v1.y + c0 * bb0.y + c1 * bb1.y;
        r.z = v0.z + v1.z + c0 * bb0.z + c1 * bb1.z;
        r.w = v0.w + v1.w + c0 * bb0.w + c1 * bb1.w;
        *(float4*)(o + f) = r;
    }
}

// ---------------- launch -------------------------------------------------------
extern "C" void kernel_launch(void* const* d_in, const int* in_sizes, int n_in,
                              void* d_out, int out_size) {
    const float* x  = (const float*)d_in[0];
    const float* gW = (const float*)d_in[1];
    const float* gb = (const float*)d_in[2];
    const float* eW = (const float*)d_in[3];
    const float* eb = (const float*)d_in[4];
    float* out = (float*)d_out;

    cudaFuncSetAttribute(k_gemm, cudaFuncAttributeMaxDynamicSharedMemorySize, SMEM_TOTAL);

    k_round<<<(NTOK * DIM) / (512 * 8), 512>>>(x);   // also zeroes counters
    dim3 tgrid(DIM / 32, DIM / 32, NE);
    k_transpose<<<tgrid, dim3(32, 8)>>>(eW);
    k_gate<<<NTOK / 32, 256>>>(x, gW, gb);
    dim3 grid(DIM / BN, NTOK / BM, NE);              // (8, 64, 8); empty tiles exit early
    k_gemm<<<grid, 256, SMEM_TOTAL>>>();
    k_combine<<<NTOK, 256>>>(eb, out);
}

// round 10
// speedup vs baseline: 3.6549x; 1.1173x over previous
#include <cuda_runtime.h>
#include <cuda_fp16.h>
#include <cstdint>

#define NTOK 8192
#define DIM  1024
#define NE   8

// GEMM tiling (fp16 operands, fp32 accum)
#define BM 128
#define BN 128
#define BK 64                  // halves per k-chunk
#define NK (DIM / BK)          // 16
#define NST 4                  // cp.async stages
#define NTHREADS 512

#define RSTRIDE_H 72           // halves per padded smem row (144B)
#define ROW_B 144
#define STAGE_B (256 * ROW_B)  // A(128 rows) + B(128 rows) = 36864 B
#define SMEM_TOK_OFF (NST * STAGE_B)            // 147456
#define SMEM_COEF_OFF (SMEM_TOK_OFF + BM * 4)   // 147968
#define SMEM_TOTAL (SMEM_COEF_OFF + BM * 4)     // 148480

// ---------------- device scratch (allocation-free rule) -----------------------
__device__ int    g_counts[NE];
__device__ int    g_list[NE][NTOK];     // entry = token*2 + slot
__device__ float  g_listc[NE][NTOK];
__device__ __half g_xh[(size_t)NTOK * DIM];        // x in fp16
__device__ __half g_wh[(size_t)NE * DIM * DIM];    // W^T in fp16: [e][f][d]

// ---------------- helpers -----------------------------------------------------
__device__ __forceinline__ uint32_t smem_u32(const void* p) {
    uint32_t a;
    asm("{ .reg .u64 t; cvta.to.shared.u64 t, %1; cvt.u32.u64 %0, t; }" : "=r"(a) : "l"(p));
    return a;
}
__device__ __forceinline__ void cpa16(uint32_t dst, const void* src) {
    asm volatile("cp.async.cg.shared.global [%0], [%1], 16;" :: "r"(dst), "l"(src) : "memory");
}
__device__ __forceinline__ void ldm_x4(uint32_t* r, uint32_t addr) {
    asm volatile("ldmatrix.sync.aligned.m8n8.x4.shared.b16 {%0,%1,%2,%3}, [%4];"
                 : "=r"(r[0]), "=r"(r[1]), "=r"(r[2]), "=r"(r[3]) : "r"(addr));
}
__device__ __forceinline__ void mma16(float* c, uint32_t a0, uint32_t a1, uint32_t a2,
                                      uint32_t a3, uint32_t b0, uint32_t b1) {
    asm volatile(
        "mma.sync.aligned.m16n8k16.row.col.f32.f16.f16.f32 "
        "{%0,%1,%2,%3}, {%4,%5,%6,%7}, {%8,%9}, {%0,%1,%2,%3};"
        : "+f"(c[0]), "+f"(c[1]), "+f"(c[2]), "+f"(c[3])
        : "r"(a0), "r"(a1), "r"(a2), "r"(a3), "r"(b0), "r"(b1));
}

// ---------------- kernel 1: x -> fp16 (+ zero counters) ------------------------
__global__ void k_round(const float* __restrict__ x) {
    if (blockIdx.x == 0 && threadIdx.x < NE) g_counts[threadIdx.x] = 0;
    size_t i = ((size_t)blockIdx.x * blockDim.x + threadIdx.x) * 8;
    float4 v0 = *(const float4*)(x + i);
    float4 v1 = *(const float4*)(x + i + 4);
    __half2 h[4];
    h[0] = __floats2half2_rn(v0.x, v0.y);
    h[1] = __floats2half2_rn(v0.z, v0.w);
    h[2] = __floats2half2_rn(v1.x, v1.y);
    h[3] = __floats2half2_rn(v1.z, v1.w);
    *(uint4*)(g_xh + i) = *(uint4*)h;
}

// ---------------- kernel 2: transpose W -> [e][f][d] fp16 ----------------------
__global__ void k_transpose(const float* __restrict__ eW) {
    __shared__ float tile[32][33];
    int e = blockIdx.z;
    int d0 = blockIdx.y * 32, f0 = blockIdx.x * 32;
    const float* src = eW + (size_t)e * DIM * DIM;
    __half* dst = g_wh + (size_t)e * DIM * DIM;
    int tx = threadIdx.x, ty = threadIdx.y;   // 32 x 8
#pragma unroll
    for (int i = 0; i < 32; i += 8)
        tile[ty + i][tx] = src[(size_t)(d0 + ty + i) * DIM + f0 + tx];
    __syncthreads();
#pragma unroll
    for (int i = 0; i < 32; i += 8)
        dst[(size_t)(f0 + ty + i) * DIM + d0 + tx] = __float2half_rn(tile[tx][ty + i]);
}

// ---------------- kernel 3: gating (4 tokens per warp) --------------------------
__global__ void k_gate(const float* __restrict__ x,
                       const float* __restrict__ gW,
                       const float* __restrict__ gb,
                       int* __restrict__ tok_e, float* __restrict__ tok_c) {
    __shared__ float sWT[NE * DIM];
    for (int i = threadIdx.x; i < NE * DIM; i += blockDim.x) {
        int d = i >> 3, e = i & 7;          // gW is [D][E]
        sWT[e * DIM + d] = gW[i];
    }
    __syncthreads();

    int warp = threadIdx.x >> 5, lane = threadIdx.x & 31;
    int t0 = blockIdx.x * 32 + warp * 4;

    float acc[4][NE];
#pragma unroll
    for (int tt = 0; tt < 4; tt++)
#pragma unroll
        for (int e = 0; e < NE; e++) acc[tt][e] = 0.f;

    for (int d = lane; d < DIM; d += 32) {
        float wv[NE];
#pragma unroll
        for (int e = 0; e < NE; e++) wv[e] = sWT[e * DIM + d];
#pragma unroll
        for (int tt = 0; tt < 4; tt++) {
            float xv = x[(size_t)(t0 + tt) * DIM + d];
#pragma unroll
            for (int e = 0; e < NE; e++) acc[tt][e] = fmaf(xv, wv[e], acc[tt][e]);
        }
    }
#pragma unroll
    for (int tt = 0; tt < 4; tt++)
#pragma unroll
        for (int e = 0; e < NE; e++)
#pragma unroll
            for (int o = 16; o; o >>= 1)
                acc[tt][e] += __shfl_xor_sync(0xffffffffu, acc[tt][e], o);

    if (lane == 0) {
#pragma unroll
        for (int tt = 0; tt < 4; tt++) {
            int t = t0 + tt;
            float s[NE], m = -1e30f;
#pragma unroll
            for (int e = 0; e < NE; e++) {
                s[e] = fmaxf(acc[tt][e] + gb[e], 1e-4f);
                m = fmaxf(m, s[e]);
            }
            float p[NE], sum = 0.f;
#pragma unroll
            for (int e = 0; e < NE; e++) { p[e] = expf(s[e] - m); sum += p[e]; }
            float inv = 1.f / sum;
#pragma unroll
            for (int e = 0; e < NE; e++) p[e] *= inv;

            int i0 = 0;
#pragma unroll
            for (int e = 1; e < NE; e++) if (p[e] > p[i0]) i0 = e;
            int i1 = (i0 == 0) ? 1 : 0;
#pragma unroll
            for (int e = 0; e < NE; e++) if (e != i0 && p[e] > p[i1]) i1 = e;

            float w0 = fmaxf(p[i0], 0.1f);
            float w1 = fmaxf(p[i1], 0.1f);
            float inv2 = 1.f / (w0 + w1);
            float c0 = w0 * inv2 * 0.5f;
            float c1 = w1 * inv2 * 0.5f;

            int p0 = atomicAdd(&g_counts[i0], 1);
            g_list[i0][p0] = t * 2;     g_listc[i0][p0] = c0;
            int p1 = atomicAdd(&g_counts[i1], 1);
            g_list[i1][p1] = t * 2 + 1; g_listc[i1][p1] = c1;
            (void)tok_e; (void)tok_c;
        }
    }
}

// ---------------- kernel 4: grouped GEMM (512 thr, ldmatrix, fused epilogue) ---
__global__ void __launch_bounds__(NTHREADS, 1) k_gemm(const float* __restrict__ eb,
                                                      float* __restrict__ out) {
    extern __shared__ char smc[];
    int e   = blockIdx.z;
    int cnt = g_counts[e];
    int m0  = blockIdx.y * BM;
    if (m0 >= cnt) return;
    int n0  = blockIdx.x * BN;

    int*   stok  = (int*)(smc + SMEM_TOK_OFF);
    float* scoef = (float*)(smc + SMEM_COEF_OFF);
    uint32_t sbase = smem_u32(smc);

    int tid  = threadIdx.x;
    int warp = tid >> 5;
    int lane = tid & 31;
    int g    = lane >> 2;
    int t4   = lane & 3;

    if (tid < BM) {
        int m = m0 + tid;
        if (m < cnt) { stok[tid] = g_list[e][m]; scoef[tid] = g_listc[e][m]; }
        else         { stok[tid] = -1;           scoef[tid] = 0.f; }
    }
    __syncthreads();

    int wm = (warp >> 2) * 32;   // 4x4 warps, 32x32 tile each
    int wn = (warp & 3) * 32;

    // global->smem: thread owns 64B of one row; rows 0-127 A, 128-255 B
    int lrow = tid >> 1, lh = tid & 1;
    const __half* gsrc;
    if (lrow < BM) {
        int atok = stok[lrow];
        gsrc = g_xh + (size_t)((atok >= 0 ? atok : 0) >> 1) * DIM;
    } else {
        gsrc = g_wh + (size_t)e * DIM * DIM + (size_t)(n0 + lrow - BM) * DIM;
    }
    gsrc += lh * 32;
    uint32_t rowdst = sbase + lrow * ROW_B + lh * 64;

#define LOAD_STAGE(kc_, st_)                                                   \
    {                                                                          \
        uint32_t d_ = rowdst + (st_) * STAGE_B;                                \
        const __half* s_ = gsrc + (kc_) * BK;                                  \
        _Pragma("unroll")                                                      \
        for (int j = 0; j < 4; j++) cpa16(d_ + j * 16, s_ + j * 8);            \
        asm volatile("cp.async.commit_group;" ::: "memory");                   \
    }

#pragma unroll
    for (int s = 0; s < NST - 1; s++) LOAD_STAGE(s, s);

    // ldmatrix per-lane address offsets (bytes, within a stage)
    // A (mt tile: 16x16 halves): lanes 0-7 m0-7 k0 | 8-15 m8-15 k0 | 16-23 m0-7 k8 | 24-31 m8-15 k8
    uint32_t a_off = (uint32_t)(wm + (lane & 15)) * ROW_B + (lane >> 4) * 16;
    // B (nt-pair tile: 16 n rows x 16 halves): lanes 0-7 n0-7 k0 | 8-15 n0-7 k8 | 16-23 n8-15 k0 | 24-31 n8-15 k8
    uint32_t b_off = (uint32_t)(BM + wn + (lane & 7) + ((lane >> 4) & 1) * 8) * ROW_B
                   + ((lane >> 3) & 1) * 16;

    float acc[2][4][4];
#pragma unroll
    for (int mt = 0; mt < 2; mt++)
#pragma unroll
        for (int nt = 0; nt < 4; nt++)
#pragma unroll
            for (int i = 0; i < 4; i++) acc[mt][nt][i] = 0.f;

    for (int kc = 0; kc < NK; kc++) {
        asm volatile("cp.async.wait_group %0;" :: "n"(NST - 2) : "memory");
        __syncthreads();

        uint32_t stg = sbase + (kc & (NST - 1)) * STAGE_B;

#pragma unroll
        for (int ks = 0; ks < BK / 16; ks++) {
            uint32_t kb = ks * 32;    // 16 halves = 32B
            uint32_t af[2][4], bf[4][2], bq[2][4];
#pragma unroll
            for (int mt = 0; mt < 2; mt++)
                ldm_x4(af[mt], stg + a_off + mt * (16 * ROW_B) + kb);
#pragma unroll
            for (int np = 0; np < 2; np++)
                ldm_x4(bq[np], stg + b_off + np * (16 * ROW_B) + kb);
            bf[0][0] = bq[0][0]; bf[0][1] = bq[0][1];
            bf[1][0] = bq[0][2]; bf[1][1] = bq[0][3];
            bf[2][0] = bq[1][0]; bf[2][1] = bq[1][1];
            bf[3][0] = bq[1][2]; bf[3][1] = bq[1][3];
#pragma unroll
            for (int mt = 0; mt < 2; mt++)
#pragma unroll
                for (int nt = 0; nt < 4; nt++)
                    mma16(acc[mt][nt], af[mt][0], af[mt][1], af[mt][2], af[mt][3],
                          bf[nt][0], bf[nt][1]);
        }

        int kn = kc + NST - 1;
        if (kn < NK) {
            LOAD_STAGE(kn, kn & (NST - 1));
        } else {
            asm volatile("cp.async.commit_group;" ::: "memory");
        }
    }

    // fused epilogue: atomicAdd coef*(row@W + bias) into out (out pre-zeroed)
    const float* ebrow = eb + (size_t)e * DIM + n0 + wn;
#pragma unroll
    for (int mt = 0; mt < 2; mt++) {
#pragma unroll
        for (int half = 0; half < 2; half++) {
            int m = wm + mt * 16 + half * 8 + g;
            if (m0 + m < cnt) {
                int token = stok[m] >> 1;
                float cf  = scoef[m];
                float* orow = out + (size_t)token * DIM + n0 + wn;
#pragma unroll
                for (int nt = 0; nt < 4; nt++) {
                    int col = nt * 8 + t4 * 2;
                    atomicAdd(orow + col,     acc[mt][nt][half * 2 + 0] * cf + cf * ebrow[col]);
                    atomicAdd(orow + col + 1, acc[mt][nt][half * 2 + 1] * cf + cf * ebrow[col + 1]);
                }
            }
        }
    }
}

// ---------------- launch -------------------------------------------------------
extern "C" void kernel_launch(void* const* d_in, const int* in_sizes, int n_in,
                              void* d_out, int out_size) {
    const float* x  = (const float*)d_in[0];
    const float* gW = (const float*)d_in[1];
    const float* gb = (const float*)d_in[2];
    const float* eW = (const float*)d_in[3];
    const float* eb = (const float*)d_in[4];
    float* out = (float*)d_out;

    cudaFuncSetAttribute(k_gemm, cudaFuncAttributeMaxDynamicSharedMemorySize, SMEM_TOTAL);

    cudaMemsetAsync(out, 0, (size_t)out_size * sizeof(float));
    k_round<<<(NTOK * DIM) / (512 * 8), 512>>>(x);   // also zeroes counters
    dim3 tgrid(DIM / 32, DIM / 32, NE);
    k_transpose<<<tgrid, dim3(32, 8)>>>(eW);
    k_gate<<<NTOK / 32, 256>>>(x, gW, gb, nullptr, nullptr);
    dim3 grid(DIM / BN, NTOK / BM, NE);              // (8, 64, 8); empty tiles exit early
    k_gemm<<<grid, NTHREADS, SMEM_TOTAL>>>(eb, out);
}

// round 15
// speedup vs baseline: 3.7377x; 1.0226x over previous
#include <cuda_runtime.h>
#include <cuda_fp16.h>
#include <cstdint>

#define NTOK 8192
#define DIM  1024
#define NE   8

// GEMM tiling (fp16 operands, fp32 accum)
#define BM 128
#define BN 128
#define BK 64                  // halves per k-chunk
#define NK (DIM / BK)          // 16
#define NST 3                  // cp.async stages
#define NTHREADS 256

#define ROW_B 144              // bytes per padded smem row
#define STAGE_B (256 * ROW_B)  // A(128 rows) + B(128 rows) = 36864 B
#define SMEM_TOK_OFF (NST * STAGE_B)            // 110592
#define SMEM_COEF_OFF (SMEM_TOK_OFF + BM * 4)   // 111104
#define SMEM_TOTAL (SMEM_COEF_OFF + BM * 4)     // 111616  (x2 CTAs = 223232 <= 228KB)

// ---------------- device scratch (allocation-free rule) -----------------------
__device__ int    g_counts[NE];
__device__ int    g_list[NE][NTOK];     // entry = token*2 + slot
__device__ float  g_listc[NE][NTOK];
__device__ __half g_xh[(size_t)NTOK * DIM];        // x in fp16
__device__ __half g_wh[(size_t)NE * DIM * DIM];    // W^T in fp16: [e][f][d]

// ---------------- helpers -----------------------------------------------------
__device__ __forceinline__ uint32_t smem_u32(const void* p) {
    uint32_t a;
    asm("{ .reg .u64 t; cvta.to.shared.u64 t, %1; cvt.u32.u64 %0, t; }" : "=r"(a) : "l"(p));
    return a;
}
__device__ __forceinline__ void cpa16(uint32_t dst, const void* src) {
    asm volatile("cp.async.cg.shared.global [%0], [%1], 16;" :: "r"(dst), "l"(src) : "memory");
}
__device__ __forceinline__ void ldm_x4(uint32_t* r, uint32_t addr) {
    asm volatile("ldmatrix.sync.aligned.m8n8.x4.shared.b16 {%0,%1,%2,%3}, [%4];"
                 : "=r"(r[0]), "=r"(r[1]), "=r"(r[2]), "=r"(r[3]) : "r"(addr));
}
__device__ __forceinline__ void mma16(float* c, uint32_t a0, uint32_t a1, uint32_t a2,
                                      uint32_t a3, uint32_t b0, uint32_t b1) {
    asm volatile(
        "mma.sync.aligned.m16n8k16.row.col.f32.f16.f16.f32 "
        "{%0,%1,%2,%3}, {%4,%5,%6,%7}, {%8,%9}, {%0,%1,%2,%3};"
        : "+f"(c[0]), "+f"(c[1]), "+f"(c[2]), "+f"(c[3])
        : "r"(a0), "r"(a1), "r"(a2), "r"(a3), "r"(b0), "r"(b1));
}
__device__ __forceinline__ void red_v2(float* p, float v0, float v1) {
    asm volatile("red.global.add.v2.f32 [%0], {%1, %2};"
                 :: "l"(p), "f"(v0), "f"(v1) : "memory");
}

// ---------------- kernel 1: x -> fp16 (+ zero counters) ------------------------
__global__ void k_round(const float* __restrict__ x) {
    if (blockIdx.x == 0 && threadIdx.x < NE) g_counts[threadIdx.x] = 0;
    size_t i = ((size_t)blockIdx.x * blockDim.x + threadIdx.x) * 8;
    float4 v0 = *(const float4*)(x + i);
    float4 v1 = *(const float4*)(x + i + 4);
    __half2 h[4];
    h[0] = __floats2half2_rn(v0.x, v0.y);
    h[1] = __floats2half2_rn(v0.z, v0.w);
    h[2] = __floats2half2_rn(v1.x, v1.y);
    h[3] = __floats2half2_rn(v1.z, v1.w);
    *(uint4*)(g_xh + i) = *(uint4*)h;
}

// ---------------- kernel 2: transpose W -> [e][f][d] fp16 ----------------------
__global__ void k_transpose(const float* __restrict__ eW) {
    __shared__ float tile[32][33];
    int e = blockIdx.z;
    int d0 = blockIdx.y * 32, f0 = blockIdx.x * 32;
    const float* src = eW + (size_t)e * DIM * DIM;
    __half* dst = g_wh + (size_t)e * DIM * DIM;
    int tx = threadIdx.x, ty = threadIdx.y;   // 32 x 8
#pragma unroll
    for (int i = 0; i < 32; i += 8)
        tile[ty + i][tx] = src[(size_t)(d0 + ty + i) * DIM + f0 + tx];
    __syncthreads();
#pragma unroll
    for (int i = 0; i < 32; i += 8)
        dst[(size_t)(f0 + ty + i) * DIM + d0 + tx] = __float2half_rn(tile[tx][ty + i]);
}

// ---------------- kernel 3: gating (4 tokens per warp) --------------------------
__global__ void k_gate(const float* __restrict__ x,
                       const float* __restrict__ gW,
                       const float* __restrict__ gb) {
    __shared__ float sWT[NE * DIM];
    for (int i = threadIdx.x; i < NE * DIM; i += blockDim.x) {
        int d = i >> 3, e = i & 7;          // gW is [D][E]
        sWT[e * DIM + d] = gW[i];
    }
    __syncthreads();

    int warp = threadIdx.x >> 5, lane = threadIdx.x & 31;
    int t0 = blockIdx.x * 32 + warp * 4;

    float acc[4][NE];
#pragma unroll
    for (int tt = 0; tt < 4; tt++)
#pragma unroll
        for (int e = 0; e < NE; e++) acc[tt][e] = 0.f;

    for (int d = lane; d < DIM; d += 32) {
        float wv[NE];
#pragma unroll
        for (int e = 0; e < NE; e++) wv[e] = sWT[e * DIM + d];
#pragma unroll
        for (int tt = 0; tt < 4; tt++) {
            float xv = x[(size_t)(t0 + tt) * DIM + d];
#pragma unroll
            for (int e = 0; e < NE; e++) acc[tt][e] = fmaf(xv, wv[e], acc[tt][e]);
        }
    }
#pragma unroll
    for (int tt = 0; tt < 4; tt++)
#pragma unroll
        for (int e = 0; e < NE; e++)
#pragma unroll
            for (int o = 16; o; o >>= 1)
                acc[tt][e] += __shfl_xor_sync(0xffffffffu, acc[tt][e], o);

    if (lane == 0) {
#pragma unroll
        for (int tt = 0; tt < 4; tt++) {
            int t = t0 + tt;
            float s[NE], m = -1e30f;
#pragma unroll
            for (int e = 0; e < NE; e++) {
                s[e] = fmaxf(acc[tt][e] + gb[e], 1e-4f);
                m = fmaxf(m, s[e]);
            }
            float p[NE], sum = 0.f;
#pragma unroll
            for (int e = 0; e < NE; e++) { p[e] = expf(s[e] - m); sum += p[e]; }
            float inv = 1.f / sum;
#pragma unroll
            for (int e = 0; e < NE; e++) p[e] *= inv;

            int i0 = 0;
#pragma unroll
            for (int e = 1; e < NE; e++) if (p[e] > p[i0]) i0 = e;
            int i1 = (i0 == 0) ? 1 : 0;
#pragma unroll
            for (int e = 0; e < NE; e++) if (e != i0 && p[e] > p[i1]) i1 = e;

            float w0 = fmaxf(p[i0], 0.1f);
            float w1 = fmaxf(p[i1], 0.1f);
            float inv2 = 1.f / (w0 + w1);
            float c0 = w0 * inv2 * 0.5f;
            float c1 = w1 * inv2 * 0.5f;

            int p0 = atomicAdd(&g_counts[i0], 1);
            g_list[i0][p0] = t * 2;     g_listc[i0][p0] = c0;
            int p1 = atomicAdd(&g_counts[i1], 1);
            g_list[i1][p1] = t * 2 + 1; g_listc[i1][p1] = c1;
        }
    }
}

// ---------------- kernel 4: grouped GEMM (256 thr, 2 CTA/SM, red.v2) -----------
__global__ void __launch_bounds__(NTHREADS, 2) k_gemm(const float* __restrict__ eb,
                                                      float* __restrict__ out) {
    extern __shared__ char smc[];
    int e   = blockIdx.z;
    int cnt = g_counts[e];
    int m0  = blockIdx.y * BM;
    if (m0 >= cnt) return;
    int n0  = blockIdx.x * BN;

    int*   stok  = (int*)(smc + SMEM_TOK_OFF);
    float* scoef = (float*)(smc + SMEM_COEF_OFF);
    uint32_t sbase = smem_u32(smc);

    int tid  = threadIdx.x;
    int warp = tid >> 5;
    int lane = tid & 31;
    int g    = lane >> 2;
    int t4   = lane & 3;

    if (tid < BM) {
        int m = m0 + tid;
        if (m < cnt) { stok[tid] = g_list[e][m]; scoef[tid] = g_listc[e][m]; }
        else         { stok[tid] = -1;           scoef[tid] = 0.f; }
    }
    __syncthreads();

    int wm = (warp >> 2) * 64;   // 2x4 warps, 64x32 tile each
    int wn = (warp & 3) * 32;

    // global->smem: thread tid owns full row tid (128B); rows 0-127 A, 128-255 B
    const __half* gsrc;
    if (tid < BM) {
        int atok = stok[tid];
        gsrc = g_xh + (size_t)((atok >= 0 ? atok : 0) >> 1) * DIM;
    } else {
        gsrc = g_wh + (size_t)e * DIM * DIM + (size_t)(n0 + tid - BM) * DIM;
    }
    uint32_t rowdst = sbase + tid * ROW_B;

#define LOAD_STAGE(kc_, st_)                                                   \
    {                                                                          \
        uint32_t d_ = rowdst + (st_) * STAGE_B;                                \
        const __half* s_ = gsrc + (kc_) * BK;                                  \
        _Pragma("unroll")                                                      \
        for (int j = 0; j < 8; j++) cpa16(d_ + j * 16, s_ + j * 8);            \
        asm volatile("cp.async.commit_group;" ::: "memory");                   \
    }

    LOAD_STAGE(0, 0);
    LOAD_STAGE(1, 1);

    // ldmatrix per-lane offsets (bytes within a stage)
    uint32_t a_off = (uint32_t)(wm + (lane & 15)) * ROW_B + (lane >> 4) * 16;
    uint32_t b_off = (uint32_t)(BM + wn + (lane & 7) + ((lane >> 4) & 1) * 8) * ROW_B
                   + ((lane >> 3) & 1) * 16;

    float acc[4][4][4];
#pragma unroll
    for (int mt = 0; mt < 4; mt++)
#pragma unroll
        for (int nt = 0; nt < 4; nt++)
#pragma unroll
            for (int i = 0; i < 4; i++) acc[mt][nt][i] = 0.f;

    int st = 0;           // stage of current chunk
    int stn = 2;          // stage for the chunk we prefetch (kc+2)
    for (int kc = 0; kc < NK; kc++) {
        asm volatile("cp.async.wait_group %0;" :: "n"(1) : "memory");
        __syncthreads();

        // prefetch chunk kc+2 into stage (kc+2)%3 == (kc-1)%3 (safe: all warps
        // finished computing chunk kc-1 before this barrier)
        if (kc + 2 < NK) {
            LOAD_STAGE(kc + 2, stn);
        } else {
            asm volatile("cp.async.commit_group;" ::: "memory");
        }

        uint32_t stg = sbase + st * STAGE_B;
#pragma unroll
        for (int ks = 0; ks < BK / 16; ks++) {
            uint32_t kb = ks * 32;    // 16 halves = 32B
            uint32_t af[4][4], bf[4][2], bq[2][4];
#pragma unroll
            for (int mt = 0; mt < 4; mt++)
                ldm_x4(af[mt], stg + a_off + mt * (16 * ROW_B) + kb);
#pragma unroll
            for (int np = 0; np < 2; np++)
                ldm_x4(bq[np], stg + b_off + np * (16 * ROW_B) + kb);
            bf[0][0] = bq[0][0]; bf[0][1] = bq[0][1];
            bf[1][0] = bq[0][2]; bf[1][1] = bq[0][3];
            bf[2][0] = bq[1][0]; bf[2][1] = bq[1][1];
            bf[3][0] = bq[1][2]; bf[3][1] = bq[1][3];
#pragma unroll
            for (int mt = 0; mt < 4; mt++)
#pragma unroll
                for (int nt = 0; nt < 4; nt++)
                    mma16(acc[mt][nt], af[mt][0], af[mt][1], af[mt][2], af[mt][3],
                          bf[nt][0], bf[nt][1]);
        }

        st  = (st == 2) ? 0 : st + 1;
        stn = (stn == 2) ? 0 : stn + 1;
    }

    // fused epilogue: red.v2 of coef*(row@W + bias) into out (pre-zeroed)
    const float* ebrow = eb + (size_t)e * DIM + n0 + wn;
#pragma unroll
    for (int mt = 0; mt < 4; mt++) {
#pragma unroll
        for (int half = 0; half < 2; half++) {
            int m = wm + mt * 16 + half * 8 + g;
            if (m0 + m < cnt) {
                int token = stok[m] >> 1;
                float cf  = scoef[m];
                float* orow = out + (size_t)token * DIM + n0 + wn;
#pragma unroll
                for (int nt = 0; nt < 4; nt++) {
                    int col = nt * 8 + t4 * 2;
                    red_v2(orow + col,
                           acc[mt][nt][half * 2 + 0] * cf + cf * ebrow[col],
                           acc[mt][nt][half * 2 + 1] * cf + cf * ebrow[col + 1]);
                }
            }
        }
    }
}

// ---------------- launch -------------------------------------------------------
extern "C" void kernel_launch(void* const* d_in, const int* in_sizes, int n_in,
                              void* d_out, int out_size) {
    const float* x  = (const float*)d_in[0];
    const float* gW = (const float*)d_in[1];
    const float* gb = (const float*)d_in[2];
    const float* eW = (const float*)d_in[3];
    const float* eb = (const float*)d_in[4];
    float* out = (float*)d_out;

    cudaFuncSetAttribute(k_gemm, cudaFuncAttributeMaxDynamicSharedMemorySize, SMEM_TOTAL);

    cudaMemsetAsync(out, 0, (size_t)out_size * sizeof(float));
    k_round<<<(NTOK * DIM) / (512 * 8), 512>>>(x);   // also zeroes counters
    dim3 tgrid(DIM / 32, DIM / 32, NE);
    k_transpose<<<tgrid, dim3(32, 8)>>>(eW);
    k_gate<<<NTOK / 32, 256>>>(x, gW, gb);
    dim3 grid(DIM / BN, NTOK / BM, NE);              // (8, 64, 8); empty tiles exit early
    k_gemm<<<grid, NTHREADS, SMEM_TOTAL>>>(eb, out);
}